// round 2
// baseline (speedup 1.0000x reference)
#include <cuda_runtime.h>
#include <cuda_bf16.h>
#include <math.h>
#include <float.h>

// Problem constants
#define BATCH   2
#define SEQ     1024
#define TOKENS  (BATCH*SEQ)      // 2048
#define DIM     2048
#define NHEADS  32
#define NKV     8
#define HD      64
#define KVDIM   (NKV*HD)         // 512
#define REP     (NHEADS/NKV)     // 4

// ---------------------------------------------------------------------------
// Scratch (no allocations allowed) — referenced DIRECTLY from device code,
// no cudaGetSymbolAddress on the host path.
// ---------------------------------------------------------------------------
__device__ float g_q [TOKENS*DIM];    // 16 MB
__device__ float g_k [TOKENS*KVDIM];  //  4 MB
__device__ float g_v [TOKENS*KVDIM];  //  4 MB
__device__ float g_ao[TOKENS*DIM];    // 16 MB  (attention output, pre wo)

// ---------------------------------------------------------------------------
// Generic SGEMM body: C[M,N] = A[M,K] @ B[K,N], all row-major fp32.
// 128x128 tile, BK=8, 256 threads, 8x8 per thread.
// Requires: M%128==0, N%128==0, K%8==0 (true for all four calls).
// ---------------------------------------------------------------------------
#define BM 128
#define BN 128
#define BK 8
#define TM 8
#define TN 8

__device__ __forceinline__
void sgemm_body(const float* __restrict__ A, const float* __restrict__ B,
                float* __restrict__ C, int M, int N, int K)
{
    __shared__ float As[BK][BM];   // transposed A tile
    __shared__ float Bs[BK][BN];

    const int tid = threadIdx.x;
    const int row0 = blockIdx.y * BM;
    const int col0 = blockIdx.x * BN;

    const int tx = tid & 15;       // 0..15 -> col group
    const int ty = tid >> 4;       // 0..15 -> row group

    // A tile load mapping: 128 rows x 8 cols = 256 float4 (2 per row)
    const int ar = tid >> 1;
    const int ac = (tid & 1) * 4;
    // B tile load mapping: 8 rows x 128 cols = 256 float4
    const int br = tid >> 5;
    const int bc = (tid & 31) * 4;

    float acc[TM][TN];
#pragma unroll
    for (int i = 0; i < TM; i++)
#pragma unroll
        for (int j = 0; j < TN; j++) acc[i][j] = 0.0f;

    for (int k0 = 0; k0 < K; k0 += BK) {
        float4 av = *reinterpret_cast<const float4*>(&A[(size_t)(row0 + ar) * K + k0 + ac]);
        As[ac + 0][ar] = av.x;
        As[ac + 1][ar] = av.y;
        As[ac + 2][ar] = av.z;
        As[ac + 3][ar] = av.w;
        float4 bv = *reinterpret_cast<const float4*>(&B[(size_t)(k0 + br) * N + col0 + bc]);
        *reinterpret_cast<float4*>(&Bs[br][bc]) = bv;
        __syncthreads();

#pragma unroll
        for (int kk = 0; kk < BK; kk++) {
            float ra[TM], rb[TN];
            float4 a0 = *reinterpret_cast<const float4*>(&As[kk][ty * TM]);
            float4 a1 = *reinterpret_cast<const float4*>(&As[kk][ty * TM + 4]);
            ra[0]=a0.x; ra[1]=a0.y; ra[2]=a0.z; ra[3]=a0.w;
            ra[4]=a1.x; ra[5]=a1.y; ra[6]=a1.z; ra[7]=a1.w;
            float4 b0 = *reinterpret_cast<const float4*>(&Bs[kk][tx * TN]);
            float4 b1 = *reinterpret_cast<const float4*>(&Bs[kk][tx * TN + 4]);
            rb[0]=b0.x; rb[1]=b0.y; rb[2]=b0.z; rb[3]=b0.w;
            rb[4]=b1.x; rb[5]=b1.y; rb[6]=b1.z; rb[7]=b1.w;
#pragma unroll
            for (int i = 0; i < TM; i++)
#pragma unroll
                for (int j = 0; j < TN; j++)
                    acc[i][j] = fmaf(ra[i], rb[j], acc[i][j]);
        }
        __syncthreads();
    }

#pragma unroll
    for (int i = 0; i < TM; i++) {
        float* crow = &C[(size_t)(row0 + ty * TM + i) * N + col0 + tx * TN];
        float4 o0 = make_float4(acc[i][0], acc[i][1], acc[i][2], acc[i][3]);
        float4 o1 = make_float4(acc[i][4], acc[i][5], acc[i][6], acc[i][7]);
        *reinterpret_cast<float4*>(crow)     = o0;
        *reinterpret_cast<float4*>(crow + 4) = o1;
    }
}

// Thin wrappers: scratch buffers bound in device code, not via host API.
__global__ __launch_bounds__(256)
void sgemm_q_kernel(const float* __restrict__ x, const float* __restrict__ wq)
{ sgemm_body(x, wq, g_q, TOKENS, DIM, DIM); }

__global__ __launch_bounds__(256)
void sgemm_k_kernel(const float* __restrict__ x, const float* __restrict__ wk)
{ sgemm_body(x, wk, g_k, TOKENS, KVDIM, DIM); }

__global__ __launch_bounds__(256)
void sgemm_v_kernel(const float* __restrict__ x, const float* __restrict__ wv)
{ sgemm_body(x, wv, g_v, TOKENS, KVDIM, DIM); }

__global__ __launch_bounds__(256)
void sgemm_o_kernel(const float* __restrict__ wo, float* __restrict__ out)
{ sgemm_body(g_ao, wo, out, TOKENS, DIM, DIM); }

// ---------------------------------------------------------------------------
// RoPE (interleaved pairs): for pair i in [0, HD/2):
//   freq = theta^(-i/(HD/2)); phase = pos * freq
//   x[2i]   = x0*c - x1*s
//   x[2i+1] = x0*s + x1*c
// x layout: [TOKENS, Hh*HD]; pos = token % SEQ
// ---------------------------------------------------------------------------
template <int Hh>
__device__ __forceinline__ void rope_body(float* __restrict__ x, int total_pairs)
{
    int idx = blockIdx.x * blockDim.x + threadIdx.x;
    if (idx >= total_pairs) return;
    int i  = idx & 31;            // pair index 0..31  (HD/2 = 32)
    int t2 = idx >> 5;
    int h  = t2 % Hh;
    int t  = t2 / Hh;
    int pos = t & (SEQ - 1);

    // freq = 10000^(-i/32)
    const float LOG_THETA_OVER_32 = 0.28782313662425572f; // ln(10000)/32
    float freq = expf(-(float)i * LOG_THETA_OVER_32);
    float phase = (float)pos * freq;
    float s, c;
    sincosf(phase, &s, &c);

    float* p = x + (size_t)t * (Hh * HD) + h * HD + 2 * i;
    float x0 = p[0], x1 = p[1];
    p[0] = x0 * c - x1 * s;
    p[1] = x0 * s + x1 * c;
}

__global__ void rope_q_kernel(int total_pairs) { rope_body<NHEADS>(g_q, total_pairs); }
__global__ void rope_k_kernel(int total_pairs) { rope_body<NKV>  (g_k, total_pairs); }

// ---------------------------------------------------------------------------
// Causal flash attention, GQA (head h reads kv head h/REP).
// grid: (SEQ/128, BATCH*NHEADS); block: 128 threads, 1 query per thread.
// q,ao layout: [TOKENS, DIM] with head h at col h*HD.
// k,v layout: [TOKENS, KVDIM] with kv head j at col j*HD.
// ---------------------------------------------------------------------------
#define QT 128     // queries per block
#define KT 32      // keys per smem tile

__global__ __launch_bounds__(128)
void attn_kernel()
{
    __shared__ float4 Ks4[KT * 16];   // [key][16 float4]
    __shared__ float4 Vs4[KT * 16];

    const float* __restrict__ q = g_q;
    const float* __restrict__ k = g_k;
    const float* __restrict__ v = g_v;
    float* __restrict__ o = g_ao;

    const int tid = threadIdx.x;
    const int qb  = blockIdx.x;
    const int bh  = blockIdx.y;
    const int b   = bh / NHEADS;
    const int h   = bh % NHEADS;
    const int j   = h / REP;

    const int qi   = qb * QT + tid;        // query position within batch
    const int qtok = b * SEQ + qi;

    // load q row into registers, pre-scaled by 1/sqrt(hd)
    float4 qv[16];
    {
        const float4* qp = reinterpret_cast<const float4*>(q + (size_t)qtok * DIM + h * HD);
        const float scale = 0.125f;  // 1/sqrt(64)
#pragma unroll
        for (int c = 0; c < 16; c++) {
            float4 t = qp[c];
            t.x *= scale; t.y *= scale; t.z *= scale; t.w *= scale;
            qv[c] = t;
        }
    }

    float m = -FLT_MAX;
    float l = 0.0f;
    float4 accv[16];
#pragma unroll
    for (int c = 0; c < 16; c++) accv[c] = make_float4(0.f, 0.f, 0.f, 0.f);

    const int ntiles = (qb + 1) * (QT / KT);      // causal: keys up to end of this q block
    const int first_masked_tile = qb * (QT / KT); // tiles before this are fully unmasked

    for (int kt = 0; kt < ntiles; kt++) {
        // cooperative load of K/V tile: KT*HD floats = 512 float4, 4 per thread
        {
            const int base_tok = b * SEQ + kt * KT;
#pragma unroll
            for (int it = 0; it < 4; it++) {
                int lin = tid + it * 128;          // 0..511
                int r = lin >> 4;                  // key row 0..31
                int c = lin & 15;                  // float4 col
                size_t g = (size_t)(base_tok + r) * (KVDIM / 4) + j * 16 + c;
                Ks4[lin] = reinterpret_cast<const float4*>(k)[g];
                Vs4[lin] = reinterpret_cast<const float4*>(v)[g];
            }
        }
        __syncthreads();

        const bool need_mask = (kt >= first_masked_tile);
        float sc[KT];
        float mt = -FLT_MAX;
#pragma unroll 4
        for (int kk = 0; kk < KT; kk++) {
            float s = 0.0f;
            const float4* kr = &Ks4[kk * 16];
#pragma unroll
            for (int c = 0; c < 16; c++) {
                float4 kv4 = kr[c];
                s = fmaf(qv[c].x, kv4.x, s);
                s = fmaf(qv[c].y, kv4.y, s);
                s = fmaf(qv[c].z, kv4.z, s);
                s = fmaf(qv[c].w, kv4.w, s);
            }
            if (need_mask && (kt * KT + kk > qi)) s = -FLT_MAX;
            sc[kk] = s;
            mt = fmaxf(mt, s);
        }

        float mnew = fmaxf(m, mt);
        float corr = __expf(m - mnew);   // 0 on first tile (m=-FLT_MAX), else <=1
        l *= corr;
#pragma unroll
        for (int c = 0; c < 16; c++) {
            accv[c].x *= corr; accv[c].y *= corr;
            accv[c].z *= corr; accv[c].w *= corr;
        }
#pragma unroll 4
        for (int kk = 0; kk < KT; kk++) {
            float p = __expf(sc[kk] - mnew);   // masked -> 0
            l += p;
            const float4* vr = &Vs4[kk * 16];
#pragma unroll
            for (int c = 0; c < 16; c++) {
                float4 vv = vr[c];
                accv[c].x = fmaf(p, vv.x, accv[c].x);
                accv[c].y = fmaf(p, vv.y, accv[c].y);
                accv[c].z = fmaf(p, vv.z, accv[c].z);
                accv[c].w = fmaf(p, vv.w, accv[c].w);
            }
        }
        m = mnew;
        __syncthreads();
    }

    const float invl = 1.0f / l;
    float4* op = reinterpret_cast<float4*>(o + (size_t)qtok * DIM + h * HD);
#pragma unroll
    for (int c = 0; c < 16; c++) {
        float4 t = accv[c];
        t.x *= invl; t.y *= invl; t.z *= invl; t.w *= invl;
        op[c] = t;
    }
}

// ---------------------------------------------------------------------------
// Launch — kernel launches ONLY, no other CUDA API calls.
// ---------------------------------------------------------------------------
extern "C" void kernel_launch(void* const* d_in, const int* in_sizes, int n_in,
                              void* d_out, int out_size)
{
    const float* x  = (const float*)d_in[0];
    const float* wq = (const float*)d_in[1];
    const float* wk = (const float*)d_in[2];
    const float* wv = (const float*)d_in[3];
    const float* wo = (const float*)d_in[4];
    float* out = (float*)d_out;

    // Projections
    {
        dim3 gq(DIM / BN,   TOKENS / BM);
        dim3 gk(KVDIM / BN, TOKENS / BM);
        sgemm_q_kernel<<<gq, 256>>>(x, wq);
        sgemm_k_kernel<<<gk, 256>>>(x, wk);
        sgemm_v_kernel<<<gk, 256>>>(x, wv);
    }

    // RoPE on q and k
    {
        int qpairs = TOKENS * NHEADS * (HD / 2);
        int kpairs = TOKENS * NKV    * (HD / 2);
        rope_q_kernel<<<(qpairs + 255) / 256, 256>>>(qpairs);
        rope_k_kernel<<<(kpairs + 255) / 256, 256>>>(kpairs);
    }

    // Attention
    {
        dim3 grid(SEQ / QT, BATCH * NHEADS);
        attn_kernel<<<grid, 128>>>();
    }

    // Output projection
    {
        dim3 go(DIM / BN, TOKENS / BM);
        sgemm_o_kernel<<<go, 256>>>(wo, out);
    }
}

// round 5
// speedup vs baseline: 2.0858x; 2.0858x over previous
#include <cuda_runtime.h>
#include <cuda_bf16.h>
#include <math.h>
#include <float.h>
#include <stdint.h>

// Problem constants
#define BATCH   2
#define SEQ     1024
#define TOKENS  (BATCH*SEQ)      // 2048
#define DIM     2048
#define NHEADS  32
#define NKV     8
#define HD      64
#define KVDIM   (NKV*HD)         // 512
#define REP     (NHEADS/NKV)     // 4

// ---------------------------------------------------------------------------
// Scratch (no allocations allowed) — referenced directly from device code.
// ---------------------------------------------------------------------------
__device__ float g_q [TOKENS*DIM];    // fp32, post-GEMM, RoPE'd in place
__device__ float g_k [TOKENS*KVDIM];
__device__ float g_v [TOKENS*KVDIM];
__device__ float g_ao[TOKENS*DIM];    // attention out, pre-wo

// bf16 split operands
__device__ __nv_bfloat16 g_xh [TOKENS*DIM],  g_xl [TOKENS*DIM];   // x
__device__ __nv_bfloat16 g_aoh[TOKENS*DIM],  g_aol[TOKENS*DIM];   // attn out
__device__ __nv_bfloat16 g_wqTh[DIM*DIM],    g_wqTl[DIM*DIM];     // wq^T [N,K]
__device__ __nv_bfloat16 g_wkTh[KVDIM*DIM],  g_wkTl[KVDIM*DIM];   // wk^T
__device__ __nv_bfloat16 g_wvTh[KVDIM*DIM],  g_wvTl[KVDIM*DIM];   // wv^T
__device__ __nv_bfloat16 g_woTh[DIM*DIM],    g_woTl[DIM*DIM];     // wo^T

// ---------------------------------------------------------------------------
// mma.sync / ldmatrix / cp.async helpers (sm_80+ PTX, valid under compute_100)
// ---------------------------------------------------------------------------
__device__ __forceinline__ uint32_t smem_u32(const void* p) {
    uint32_t a;
    asm("{ .reg .u64 t; cvta.to.shared.u64 t, %1; cvt.u32.u64 %0, t; }" : "=r"(a) : "l"(p));
    return a;
}
__device__ __forceinline__ void ldsm_x4(uint32_t (&r)[4], uint32_t addr) {
    asm volatile("ldmatrix.sync.aligned.m8n8.x4.shared.b16 {%0,%1,%2,%3}, [%4];"
                 : "=r"(r[0]), "=r"(r[1]), "=r"(r[2]), "=r"(r[3]) : "r"(addr));
}
__device__ __forceinline__ void mma16816(float (&d)[4], const uint32_t* a, const uint32_t* b) {
    asm volatile("mma.sync.aligned.m16n8k16.row.col.f32.bf16.bf16.f32 "
                 "{%0,%1,%2,%3}, {%4,%5,%6,%7}, {%8,%9}, {%0,%1,%2,%3};"
                 : "+f"(d[0]), "+f"(d[1]), "+f"(d[2]), "+f"(d[3])
                 : "r"(a[0]), "r"(a[1]), "r"(a[2]), "r"(a[3]), "r"(b[0]), "r"(b[1]));
}
#define CP_ASYNC16(smem, gptr) \
    asm volatile("cp.async.cg.shared.global [%0], [%1], 16;" :: "r"(smem), "l"(gptr))
#define CP_COMMIT() asm volatile("cp.async.commit_group;" ::: "memory")
#define CP_WAIT1()  asm volatile("cp.async.wait_group 1;" ::: "memory")
#define CP_WAIT0()  asm volatile("cp.async.wait_group 0;" ::: "memory")

// ---------------------------------------------------------------------------
// bf16-split GEMM on mma.sync: C[M,N] = A[M,K] @ B[N,K]^T
// Block 128x128, BK=32, 8 warps (warp tile 64x32), 3-stage cp.async pipeline.
// SMEM stage: Ah | Al | Bh | Bl, each 128x32 bf16 = 8KB -> 32KB/stage.
// Swizzle: 16B slot = g ^ ((row>>1)&3)  (conflict-free stores + ldmatrix).
// ---------------------------------------------------------------------------
#define BKC 32
#define COMP_BYTES 8192
#define STAGE_BYTES (4*COMP_BYTES)   // 32KB
#define NSTAGES 3
#define GEMM_SMEM_TOTAL (NSTAGES*STAGE_BYTES)  // 96KB

__device__ __forceinline__
void stage_load(uint32_t sb, int stage,
                const __nv_bfloat16* __restrict__ Ah, const __nv_bfloat16* __restrict__ Al,
                const __nv_bfloat16* __restrict__ Bh, const __nv_bfloat16* __restrict__ Bl,
                int m0, int n0, int K, int k0, int tid)
{
    const uint32_t soff = sb + stage * STAGE_BYTES;
#pragma unroll
    for (int i = 0; i < 2; i++) {
        int lin = tid + i * 256;          // 0..511
        int row = lin >> 2;               // 0..127
        int g   = lin & 3;                // 16B chunk within 64B row
        int slot = g ^ ((row >> 1) & 3);
        uint32_t d = soff + row * 64 + slot * 16;
        const __nv_bfloat16* pa = Ah + (size_t)(m0 + row) * K + k0 + g * 8;
        const __nv_bfloat16* pl = Al + (size_t)(m0 + row) * K + k0 + g * 8;
        const __nv_bfloat16* pb = Bh + (size_t)(n0 + row) * K + k0 + g * 8;
        const __nv_bfloat16* pc = Bl + (size_t)(n0 + row) * K + k0 + g * 8;
        CP_ASYNC16(d + 0*COMP_BYTES, pa);
        CP_ASYNC16(d + 1*COMP_BYTES, pl);
        CP_ASYNC16(d + 2*COMP_BYTES, pb);
        CP_ASYNC16(d + 3*COMP_BYTES, pc);
    }
}

__device__ __forceinline__
void gemm_mma_body(const __nv_bfloat16* __restrict__ Ah, const __nv_bfloat16* __restrict__ Al,
                   const __nv_bfloat16* __restrict__ Bh, const __nv_bfloat16* __restrict__ Bl,
                   float* __restrict__ C, int K, int N)
{
    extern __shared__ char smem[];
    const uint32_t sb = smem_u32(smem);
    const int tid  = threadIdx.x;
    const int wid  = tid >> 5;
    const int lane = tid & 31;
    const int m0 = blockIdx.y * 128;
    const int n0 = blockIdx.x * 128;

    const int warp_m = wid & 1;     // 2 warps over M (64 rows each)
    const int warp_n = wid >> 1;    // 4 warps over N (32 cols each)

    float acc[4][4][4];
#pragma unroll
    for (int i = 0; i < 4; i++)
#pragma unroll
        for (int j = 0; j < 4; j++)
#pragma unroll
            for (int r = 0; r < 4; r++) acc[i][j][r] = 0.0f;

    const int nch = K / BKC;

    stage_load(sb, 0, Ah, Al, Bh, Bl, m0, n0, K, 0, tid);   CP_COMMIT();
    stage_load(sb, 1, Ah, Al, Bh, Bl, m0, n0, K, BKC, tid); CP_COMMIT();

    // Precompute ldmatrix lane addressing (stage-relative offsets)
    // A: row = m_base + (lane&15), chunk = ks*2 + (lane>>4)
    const int a_row = warp_m * 64 + (lane & 15);
    const int a_chk = lane >> 4;                 // 0/1
    // B: row = n_base + (lane&7) + ((lane&16)>>1), chunk = ks*2 + ((lane>>3)&1)
    const int b_row = warp_n * 32 + (lane & 7) + ((lane & 16) >> 1);
    const int b_chk = (lane >> 3) & 1;

    for (int ch = 0; ch < nch; ch++) {
        CP_WAIT1();
        __syncthreads();
        if (ch + 2 < nch) {
            stage_load(sb, (ch + 2) % NSTAGES, Ah, Al, Bh, Bl, m0, n0, K, (ch + 2) * BKC, tid);
        }
        CP_COMMIT();

        const uint32_t stg = sb + (ch % NSTAGES) * STAGE_BYTES;
#pragma unroll
        for (int ks = 0; ks < 2; ks++) {
            // ---- A-hi fragments (4 m-tiles) ----
            uint32_t aH[4][4];
#pragma unroll
            for (int mi = 0; mi < 4; mi++) {
                int row = a_row + mi * 16;
                int c = ks * 2 + a_chk;
                int slot = c ^ ((row >> 1) & 3);
                ldsm_x4(aH[mi], stg + 0*COMP_BYTES + row * 64 + slot * 16);
            }
            // ---- B-hi fragments (4 n8 frags via 2 ldmatrix) ----
            uint32_t bH[2][4];
#pragma unroll
            for (int ni = 0; ni < 2; ni++) {
                int row = b_row + ni * 16;
                int c = ks * 2 + b_chk;
                int slot = c ^ ((row >> 1) & 3);
                ldsm_x4(bH[ni], stg + 2*COMP_BYTES + row * 64 + slot * 16);
            }
#pragma unroll
            for (int mi = 0; mi < 4; mi++)
#pragma unroll
                for (int nj = 0; nj < 4; nj++)
                    mma16816(acc[mi][nj], aH[mi], &bH[nj >> 1][(nj & 1) * 2]);

            // ---- B-lo, Ah*Bl ----
            uint32_t bL[2][4];
#pragma unroll
            for (int ni = 0; ni < 2; ni++) {
                int row = b_row + ni * 16;
                int c = ks * 2 + b_chk;
                int slot = c ^ ((row >> 1) & 3);
                ldsm_x4(bL[ni], stg + 3*COMP_BYTES + row * 64 + slot * 16);
            }
#pragma unroll
            for (int mi = 0; mi < 4; mi++)
#pragma unroll
                for (int nj = 0; nj < 4; nj++)
                    mma16816(acc[mi][nj], aH[mi], &bL[nj >> 1][(nj & 1) * 2]);

            // ---- A-lo, Al*Bh ----
#pragma unroll
            for (int mi = 0; mi < 4; mi++) {
                uint32_t aL[4];
                int row = a_row + mi * 16;
                int c = ks * 2 + a_chk;
                int slot = c ^ ((row >> 1) & 3);
                ldsm_x4(aL, stg + 1*COMP_BYTES + row * 64 + slot * 16);
#pragma unroll
                for (int nj = 0; nj < 4; nj++)
                    mma16816(acc[mi][nj], aL, &bH[nj >> 1][(nj & 1) * 2]);
            }
        }
        __syncthreads();
    }
    CP_WAIT0();

    // Epilogue: write fp32 C
    const int groupID = lane >> 2;
    const int tig = lane & 3;
#pragma unroll
    for (int mi = 0; mi < 4; mi++) {
        int row = m0 + warp_m * 64 + mi * 16 + groupID;
#pragma unroll
        for (int nj = 0; nj < 4; nj++) {
            int col = n0 + warp_n * 32 + nj * 8 + tig * 2;
            float2* p0 = reinterpret_cast<float2*>(C + (size_t)row * N + col);
            float2* p1 = reinterpret_cast<float2*>(C + (size_t)(row + 8) * N + col);
            *p0 = make_float2(acc[mi][nj][0], acc[mi][nj][1]);
            *p1 = make_float2(acc[mi][nj][2], acc[mi][nj][3]);
        }
    }
}

__global__ __launch_bounds__(256, 2)
void gemm_q_mm() { gemm_mma_body(g_xh, g_xl, g_wqTh, g_wqTl, g_q, DIM, DIM); }
__global__ __launch_bounds__(256, 2)
void gemm_k_mm() { gemm_mma_body(g_xh, g_xl, g_wkTh, g_wkTl, g_k, DIM, KVDIM); }
__global__ __launch_bounds__(256, 2)
void gemm_v_mm() { gemm_mma_body(g_xh, g_xl, g_wvTh, g_wvTl, g_v, DIM, KVDIM); }
__global__ __launch_bounds__(256, 2)
void gemm_o_mm(float* __restrict__ out) { gemm_mma_body(g_aoh, g_aol, g_woTh, g_woTl, out, DIM, DIM); }

// ---------------------------------------------------------------------------
// fp32 -> bf16 hi/lo split
// ---------------------------------------------------------------------------
__device__ __forceinline__ void split1(float a, __nv_bfloat16& h, __nv_bfloat16& l) {
    h = __float2bfloat16(a);
    l = __float2bfloat16(a - __bfloat162float(h));
}
__device__ __forceinline__
void convert_split_body(const float* __restrict__ in, __nv_bfloat16* __restrict__ hi,
                        __nv_bfloat16* __restrict__ lo, int n)
{
    int idx = blockIdx.x * blockDim.x + threadIdx.x;
    if (idx < n) split1(in[idx], hi[idx], lo[idx]);
}
__global__ void convert_x_kernel (const float* __restrict__ x) { convert_split_body(x, g_xh, g_xl, TOKENS*DIM); }
__global__ void convert_ao_kernel()                            { convert_split_body(g_ao, g_aoh, g_aol, TOKENS*DIM); }

// transpose + split: w[K,N] -> wT_hi/lo[N,K]
__device__ __forceinline__
void transpose_split_body(const float* __restrict__ w, __nv_bfloat16* __restrict__ oh,
                          __nv_bfloat16* __restrict__ ol, int K, int N)
{
    __shared__ float tile[32][33];
    const int tx = threadIdx.x, ty = threadIdx.y;
    const int n0 = blockIdx.x * 32, k0 = blockIdx.y * 32;
#pragma unroll
    for (int j = 0; j < 4; j++) {
        int k = k0 + ty + j * 8;
        tile[ty + j * 8][tx] = w[(size_t)k * N + n0 + tx];
    }
    __syncthreads();
#pragma unroll
    for (int j = 0; j < 4; j++) {
        int n = n0 + ty + j * 8;
        float a = tile[tx][ty + j * 8];
        __nv_bfloat16 h, l; split1(a, h, l);
        oh[(size_t)n * K + k0 + tx] = h;
        ol[(size_t)n * K + k0 + tx] = l;
    }
}
__global__ void tsplit_wq(const float* __restrict__ w) { transpose_split_body(w, g_wqTh, g_wqTl, DIM, DIM); }
__global__ void tsplit_wk(const float* __restrict__ w) { transpose_split_body(w, g_wkTh, g_wkTl, DIM, KVDIM); }
__global__ void tsplit_wv(const float* __restrict__ w) { transpose_split_body(w, g_wvTh, g_wvTl, DIM, KVDIM); }
__global__ void tsplit_wo(const float* __restrict__ w) { transpose_split_body(w, g_woTh, g_woTl, DIM, DIM); }

// ---------------------------------------------------------------------------
// RoPE (interleaved pairs), pos = token % SEQ
// ---------------------------------------------------------------------------
template <int Hh>
__device__ __forceinline__ void rope_body(float* __restrict__ x, int total_pairs)
{
    int idx = blockIdx.x * blockDim.x + threadIdx.x;
    if (idx >= total_pairs) return;
    int i  = idx & 31;
    int t2 = idx >> 5;
    int h  = t2 % Hh;
    int t  = t2 / Hh;
    int pos = t & (SEQ - 1);
    const float LOG_THETA_OVER_32 = 0.28782313662425572f; // ln(10000)/32
    float freq = expf(-(float)i * LOG_THETA_OVER_32);
    float phase = (float)pos * freq;
    float s, c;
    sincosf(phase, &s, &c);
    float* p = x + (size_t)t * (Hh * HD) + h * HD + 2 * i;
    float x0 = p[0], x1 = p[1];
    p[0] = x0 * c - x1 * s;
    p[1] = x0 * s + x1 * c;
}
__global__ void rope_q_kernel(int total_pairs) { rope_body<NHEADS>(g_q, total_pairs); }
__global__ void rope_k_kernel(int total_pairs) { rope_body<NKV>  (g_k, total_pairs); }

// ---------------------------------------------------------------------------
// Causal flash attention, GQA. 1 query/thread, fp32.
// ---------------------------------------------------------------------------
#define QT 128
#define KT 32

__global__ __launch_bounds__(128)
void attn_kernel()
{
    __shared__ float4 Ks4[KT * 16];
    __shared__ float4 Vs4[KT * 16];

    const float* __restrict__ q = g_q;
    const float* __restrict__ k = g_k;
    const float* __restrict__ v = g_v;
    float* __restrict__ o = g_ao;

    const int tid = threadIdx.x;
    const int qb  = blockIdx.x;
    const int bh  = blockIdx.y;
    const int b   = bh / NHEADS;
    const int h   = bh % NHEADS;
    const int j   = h / REP;

    const int qi   = qb * QT + tid;
    const int qtok = b * SEQ + qi;

    float4 qv[16];
    {
        const float4* qp = reinterpret_cast<const float4*>(q + (size_t)qtok * DIM + h * HD);
        const float scale = 0.125f;
#pragma unroll
        for (int c = 0; c < 16; c++) {
            float4 t = qp[c];
            t.x *= scale; t.y *= scale; t.z *= scale; t.w *= scale;
            qv[c] = t;
        }
    }

    float m = -FLT_MAX;
    float l = 0.0f;
    float4 accv[16];
#pragma unroll
    for (int c = 0; c < 16; c++) accv[c] = make_float4(0.f, 0.f, 0.f, 0.f);

    const int ntiles = (qb + 1) * (QT / KT);
    const int first_masked_tile = qb * (QT / KT);

    for (int kt = 0; kt < ntiles; kt++) {
        {
            const int base_tok = b * SEQ + kt * KT;
#pragma unroll
            for (int it = 0; it < 4; it++) {
                int lin = tid + it * 128;
                int r = lin >> 4;
                int c = lin & 15;
                size_t g = (size_t)(base_tok + r) * (KVDIM / 4) + j * 16 + c;
                Ks4[lin] = reinterpret_cast<const float4*>(k)[g];
                Vs4[lin] = reinterpret_cast<const float4*>(v)[g];
            }
        }
        __syncthreads();

        const bool need_mask = (kt >= first_masked_tile);
        float sc[KT];
        float mt = -FLT_MAX;
#pragma unroll 4
        for (int kk = 0; kk < KT; kk++) {
            float s = 0.0f;
            const float4* kr = &Ks4[kk * 16];
#pragma unroll
            for (int c = 0; c < 16; c++) {
                float4 kv4 = kr[c];
                s = fmaf(qv[c].x, kv4.x, s);
                s = fmaf(qv[c].y, kv4.y, s);
                s = fmaf(qv[c].z, kv4.z, s);
                s = fmaf(qv[c].w, kv4.w, s);
            }
            if (need_mask && (kt * KT + kk > qi)) s = -FLT_MAX;
            sc[kk] = s;
            mt = fmaxf(mt, s);
        }

        float mnew = fmaxf(m, mt);
        float corr = __expf(m - mnew);
        l *= corr;
#pragma unroll
        for (int c = 0; c < 16; c++) {
            accv[c].x *= corr; accv[c].y *= corr;
            accv[c].z *= corr; accv[c].w *= corr;
        }
#pragma unroll 4
        for (int kk = 0; kk < KT; kk++) {
            float p = __expf(sc[kk] - mnew);
            l += p;
            const float4* vr = &Vs4[kk * 16];
#pragma unroll
            for (int c = 0; c < 16; c++) {
                float4 vv = vr[c];
                accv[c].x = fmaf(p, vv.x, accv[c].x);
                accv[c].y = fmaf(p, vv.y, accv[c].y);
                accv[c].z = fmaf(p, vv.z, accv[c].z);
                accv[c].w = fmaf(p, vv.w, accv[c].w);
            }
        }
        m = mnew;
        __syncthreads();
    }

    const float invl = 1.0f / l;
    float4* op = reinterpret_cast<float4*>(o + (size_t)qtok * DIM + h * HD);
#pragma unroll
    for (int c = 0; c < 16; c++) {
        float4 t = accv[c];
        t.x *= invl; t.y *= invl; t.z *= invl; t.w *= invl;
        op[c] = t;
    }
}

// ---------------------------------------------------------------------------
// Launch
// ---------------------------------------------------------------------------
extern "C" void kernel_launch(void* const* d_in, const int* in_sizes, int n_in,
                              void* d_out, int out_size)
{
    const float* x  = (const float*)d_in[0];
    const float* wq = (const float*)d_in[1];
    const float* wk = (const float*)d_in[2];
    const float* wv = (const float*)d_in[3];
    const float* wo = (const float*)d_in[4];
    float* out = (float*)d_out;

    // >48KB dynamic smem opt-in for the GEMMs (host-side attribute, not an alloc)
    cudaFuncSetAttribute(gemm_q_mm, cudaFuncAttributeMaxDynamicSharedMemorySize, GEMM_SMEM_TOTAL);
    cudaFuncSetAttribute(gemm_k_mm, cudaFuncAttributeMaxDynamicSharedMemorySize, GEMM_SMEM_TOTAL);
    cudaFuncSetAttribute(gemm_v_mm, cudaFuncAttributeMaxDynamicSharedMemorySize, GEMM_SMEM_TOTAL);
    cudaFuncSetAttribute(gemm_o_mm, cudaFuncAttributeMaxDynamicSharedMemorySize, GEMM_SMEM_TOTAL);

    // 1) Convert/split inputs
    {
        dim3 tb(32, 8);
        convert_x_kernel<<<(TOKENS*DIM + 255)/256, 256>>>(x);
        tsplit_wq<<<dim3(DIM/32,   DIM/32), tb>>>(wq);
        tsplit_wk<<<dim3(KVDIM/32, DIM/32), tb>>>(wk);
        tsplit_wv<<<dim3(KVDIM/32, DIM/32), tb>>>(wv);
        tsplit_wo<<<dim3(DIM/32,   DIM/32), tb>>>(wo);
    }

    // 2) Projections on tensor cores (mma.sync)
    gemm_q_mm<<<dim3(DIM/128,   TOKENS/128), 256, GEMM_SMEM_TOTAL>>>();
    gemm_k_mm<<<dim3(KVDIM/128, TOKENS/128), 256, GEMM_SMEM_TOTAL>>>();
    gemm_v_mm<<<dim3(KVDIM/128, TOKENS/128), 256, GEMM_SMEM_TOTAL>>>();

    // 3) RoPE on q and k
    {
        int qpairs = TOKENS * NHEADS * (HD / 2);
        int kpairs = TOKENS * NKV    * (HD / 2);
        rope_q_kernel<<<(qpairs + 255) / 256, 256>>>(qpairs);
        rope_k_kernel<<<(kpairs + 255) / 256, 256>>>(kpairs);
    }

    // 4) Attention (fp32 flash)
    attn_kernel<<<dim3(SEQ / QT, BATCH * NHEADS), 128>>>();

    // 5) Split attention output, output projection
    convert_ao_kernel<<<(TOKENS*DIM + 255)/256, 256>>>();
    gemm_o_mm<<<dim3(DIM/128, TOKENS/128), 256, GEMM_SMEM_TOTAL>>>(out);
}

// round 7
// speedup vs baseline: 3.2412x; 1.5539x over previous
#include <cuda_runtime.h>
#include <cuda_bf16.h>
#include <math.h>
#include <float.h>
#include <stdint.h>

// Problem constants
#define BATCH   2
#define SEQ     1024
#define TOKENS  (BATCH*SEQ)      // 2048
#define DIM     2048
#define NHEADS  32
#define NKV     8
#define HD      64
#define KVDIM   (NKV*HD)         // 512
#define REP     (NHEADS/NKV)     // 4

// ---------------------------------------------------------------------------
// Scratch (no allocations) — referenced directly from device code.
// ---------------------------------------------------------------------------
__device__ float g_q [TOKENS*DIM];    // fp32 q proj (pre-rope)
__device__ float g_k [TOKENS*KVDIM];  // fp32 k proj (pre-rope)

__device__ __nv_bfloat16 g_xh [TOKENS*DIM],   g_xl [TOKENS*DIM];    // x split
__device__ __nv_bfloat16 g_aoh[TOKENS*DIM],   g_aol[TOKENS*DIM];    // attn out split
__device__ __nv_bfloat16 g_qh [TOKENS*DIM],   g_ql [TOKENS*DIM];    // q rope+scale split
__device__ __nv_bfloat16 g_kh [TOKENS*KVDIM], g_kl [TOKENS*KVDIM];  // k rope split
__device__ __nv_bfloat16 g_vh [TOKENS*KVDIM], g_vl [TOKENS*KVDIM];  // v split
__device__ __nv_bfloat16 g_wqTh[DIM*DIM],     g_wqTl[DIM*DIM];      // wq^T [N,K]
__device__ __nv_bfloat16 g_wkTh[KVDIM*DIM],   g_wkTl[KVDIM*DIM];
__device__ __nv_bfloat16 g_wvTh[KVDIM*DIM],   g_wvTl[KVDIM*DIM];
__device__ __nv_bfloat16 g_woTh[DIM*DIM],     g_woTl[DIM*DIM];

// ---------------------------------------------------------------------------
// mma.sync / ldmatrix / cp.async helpers (sm_80+ PTX, valid under compute_100)
// ---------------------------------------------------------------------------
__device__ __forceinline__ uint32_t smem_u32(const void* p) {
    uint32_t a;
    asm("{ .reg .u64 t; cvta.to.shared.u64 t, %1; cvt.u32.u64 %0, t; }" : "=r"(a) : "l"(p));
    return a;
}
__device__ __forceinline__ void ldsm_x4(uint32_t (&r)[4], uint32_t addr) {
    asm volatile("ldmatrix.sync.aligned.m8n8.x4.shared.b16 {%0,%1,%2,%3}, [%4];"
                 : "=r"(r[0]), "=r"(r[1]), "=r"(r[2]), "=r"(r[3]) : "r"(addr));
}
__device__ __forceinline__ void ldsm_x4_t(uint32_t (&r)[4], uint32_t addr) {
    asm volatile("ldmatrix.sync.aligned.m8n8.x4.trans.shared.b16 {%0,%1,%2,%3}, [%4];"
                 : "=r"(r[0]), "=r"(r[1]), "=r"(r[2]), "=r"(r[3]) : "r"(addr));
}
__device__ __forceinline__ void mma16816(float (&d)[4], const uint32_t* a, const uint32_t* b) {
    asm volatile("mma.sync.aligned.m16n8k16.row.col.f32.bf16.bf16.f32 "
                 "{%0,%1,%2,%3}, {%4,%5,%6,%7}, {%8,%9}, {%0,%1,%2,%3};"
                 : "+f"(d[0]), "+f"(d[1]), "+f"(d[2]), "+f"(d[3])
                 : "r"(a[0]), "r"(a[1]), "r"(a[2]), "r"(a[3]), "r"(b[0]), "r"(b[1]));
}
#define CP_ASYNC16(smem, gptr) \
    asm volatile("cp.async.cg.shared.global [%0], [%1], 16;" :: "r"(smem), "l"(gptr))
#define CP_COMMIT() asm volatile("cp.async.commit_group;" ::: "memory")
#define CP_WAIT1()  asm volatile("cp.async.wait_group 1;" ::: "memory")
#define CP_WAIT0()  asm volatile("cp.async.wait_group 0;" ::: "memory")

#define SWZ128(off) ((off) ^ (((off) >> 3) & 0x70))

__device__ __forceinline__ void split1(float a, __nv_bfloat16& h, __nv_bfloat16& l) {
    h = __float2bfloat16(a);
    l = __float2bfloat16(a - __bfloat162float(h));
}
// split-pack pair (x,y) -> hi bf16x2, lo bf16x2
__device__ __forceinline__ void split_pack2(float x, float y, uint32_t& hi, uint32_t& lo) {
    __nv_bfloat16 hx, lx, hy, ly;
    split1(x, hx, lx);
    split1(y, hy, ly);
    __nv_bfloat162 th; th.x = hx; th.y = hy;
    __nv_bfloat162 tl; tl.x = lx; tl.y = ly;
    hi = *reinterpret_cast<uint32_t*>(&th);
    lo = *reinterpret_cast<uint32_t*>(&tl);
}

// ---------------------------------------------------------------------------
// bf16-split GEMM on mma.sync: C[M,N] = A[M,K] @ B[N,K]^T
// Block 128x128, BK=32, 8 warps (64x32 warp tile), 3-stage cp.async pipeline.
// OM=0: fp32 C.  OM=1: split bf16 (Ch,Cl).
// ---------------------------------------------------------------------------
#define BKC 32
#define COMP_BYTES 8192
#define STAGE_BYTES (4*COMP_BYTES)   // 32KB
#define NSTAGES 3
#define GEMM_SMEM_TOTAL (NSTAGES*STAGE_BYTES)  // 96KB

__device__ __forceinline__
void stage_load(uint32_t sb, int stage,
                const __nv_bfloat16* __restrict__ Ah, const __nv_bfloat16* __restrict__ Al,
                const __nv_bfloat16* __restrict__ Bh, const __nv_bfloat16* __restrict__ Bl,
                int m0, int n0, int K, int k0, int tid)
{
    const uint32_t soff = sb + stage * STAGE_BYTES;
#pragma unroll
    for (int i = 0; i < 2; i++) {
        int lin = tid + i * 256;
        int row = lin >> 2;
        int g   = lin & 3;
        int slot = g ^ ((row >> 1) & 3);
        uint32_t d = soff + row * 64 + slot * 16;
        const __nv_bfloat16* pa = Ah + (size_t)(m0 + row) * K + k0 + g * 8;
        const __nv_bfloat16* pl = Al + (size_t)(m0 + row) * K + k0 + g * 8;
        const __nv_bfloat16* pb = Bh + (size_t)(n0 + row) * K + k0 + g * 8;
        const __nv_bfloat16* pc = Bl + (size_t)(n0 + row) * K + k0 + g * 8;
        CP_ASYNC16(d + 0*COMP_BYTES, pa);
        CP_ASYNC16(d + 1*COMP_BYTES, pl);
        CP_ASYNC16(d + 2*COMP_BYTES, pb);
        CP_ASYNC16(d + 3*COMP_BYTES, pc);
    }
}

template<int OM>
__device__ __forceinline__
void gemm_mma_body(const __nv_bfloat16* __restrict__ Ah, const __nv_bfloat16* __restrict__ Al,
                   const __nv_bfloat16* __restrict__ Bh, const __nv_bfloat16* __restrict__ Bl,
                   float* __restrict__ C, __nv_bfloat16* __restrict__ Ch,
                   __nv_bfloat16* __restrict__ Cl, int K, int N)
{
    extern __shared__ char smem[];
    const uint32_t sb = smem_u32(smem);
    const int tid  = threadIdx.x;
    const int wid  = tid >> 5;
    const int lane = tid & 31;
    const int m0 = blockIdx.y * 128;
    const int n0 = blockIdx.x * 128;

    const int warp_m = wid & 1;
    const int warp_n = wid >> 1;

    float acc[4][4][4];
#pragma unroll
    for (int i = 0; i < 4; i++)
#pragma unroll
        for (int j = 0; j < 4; j++)
#pragma unroll
            for (int r = 0; r < 4; r++) acc[i][j][r] = 0.0f;

    const int nch = K / BKC;

    stage_load(sb, 0, Ah, Al, Bh, Bl, m0, n0, K, 0, tid);   CP_COMMIT();
    stage_load(sb, 1, Ah, Al, Bh, Bl, m0, n0, K, BKC, tid); CP_COMMIT();

    const int a_row = warp_m * 64 + (lane & 15);
    const int a_chk = lane >> 4;
    const int b_row = warp_n * 32 + (lane & 7) + ((lane & 16) >> 1);
    const int b_chk = (lane >> 3) & 1;

    for (int ch = 0; ch < nch; ch++) {
        CP_WAIT1();
        __syncthreads();
        if (ch + 2 < nch) {
            stage_load(sb, (ch + 2) % NSTAGES, Ah, Al, Bh, Bl, m0, n0, K, (ch + 2) * BKC, tid);
        }
        CP_COMMIT();

        const uint32_t stg = sb + (ch % NSTAGES) * STAGE_BYTES;
#pragma unroll
        for (int ks = 0; ks < 2; ks++) {
            uint32_t aH[4][4];
#pragma unroll
            for (int mi = 0; mi < 4; mi++) {
                int row = a_row + mi * 16;
                int c = ks * 2 + a_chk;
                int slot = c ^ ((row >> 1) & 3);
                ldsm_x4(aH[mi], stg + 0*COMP_BYTES + row * 64 + slot * 16);
            }
            uint32_t bH[2][4];
#pragma unroll
            for (int ni = 0; ni < 2; ni++) {
                int row = b_row + ni * 16;
                int c = ks * 2 + b_chk;
                int slot = c ^ ((row >> 1) & 3);
                ldsm_x4(bH[ni], stg + 2*COMP_BYTES + row * 64 + slot * 16);
            }
#pragma unroll
            for (int mi = 0; mi < 4; mi++)
#pragma unroll
                for (int nj = 0; nj < 4; nj++)
                    mma16816(acc[mi][nj], aH[mi], &bH[nj >> 1][(nj & 1) * 2]);

            uint32_t bL[2][4];
#pragma unroll
            for (int ni = 0; ni < 2; ni++) {
                int row = b_row + ni * 16;
                int c = ks * 2 + b_chk;
                int slot = c ^ ((row >> 1) & 3);
                ldsm_x4(bL[ni], stg + 3*COMP_BYTES + row * 64 + slot * 16);
            }
#pragma unroll
            for (int mi = 0; mi < 4; mi++)
#pragma unroll
                for (int nj = 0; nj < 4; nj++)
                    mma16816(acc[mi][nj], aH[mi], &bL[nj >> 1][(nj & 1) * 2]);

#pragma unroll
            for (int mi = 0; mi < 4; mi++) {
                uint32_t aL[4];
                int row = a_row + mi * 16;
                int c = ks * 2 + a_chk;
                int slot = c ^ ((row >> 1) & 3);
                ldsm_x4(aL, stg + 1*COMP_BYTES + row * 64 + slot * 16);
#pragma unroll
                for (int nj = 0; nj < 4; nj++)
                    mma16816(acc[mi][nj], aL, &bH[nj >> 1][(nj & 1) * 2]);
            }
        }
        __syncthreads();
    }
    CP_WAIT0();

    const int groupID = lane >> 2;
    const int tig = lane & 3;
#pragma unroll
    for (int mi = 0; mi < 4; mi++) {
        int row = m0 + warp_m * 64 + mi * 16 + groupID;
#pragma unroll
        for (int nj = 0; nj < 4; nj++) {
            int col = n0 + warp_n * 32 + nj * 8 + tig * 2;
            if (OM == 0) {
                float2* p0 = reinterpret_cast<float2*>(C + (size_t)row * N + col);
                float2* p1 = reinterpret_cast<float2*>(C + (size_t)(row + 8) * N + col);
                *p0 = make_float2(acc[mi][nj][0], acc[mi][nj][1]);
                *p1 = make_float2(acc[mi][nj][2], acc[mi][nj][3]);
            } else {
                uint32_t h0, l0, h1, l1;
                split_pack2(acc[mi][nj][0], acc[mi][nj][1], h0, l0);
                split_pack2(acc[mi][nj][2], acc[mi][nj][3], h1, l1);
                *reinterpret_cast<uint32_t*>(Ch + (size_t)row * N + col)       = h0;
                *reinterpret_cast<uint32_t*>(Cl + (size_t)row * N + col)       = l0;
                *reinterpret_cast<uint32_t*>(Ch + (size_t)(row + 8) * N + col) = h1;
                *reinterpret_cast<uint32_t*>(Cl + (size_t)(row + 8) * N + col) = l1;
            }
        }
    }
}

__global__ __launch_bounds__(256, 2)
void gemm_q_mm() { gemm_mma_body<0>(g_xh, g_xl, g_wqTh, g_wqTl, g_q, nullptr, nullptr, DIM, DIM); }
__global__ __launch_bounds__(256, 2)
void gemm_k_mm() { gemm_mma_body<0>(g_xh, g_xl, g_wkTh, g_wkTl, g_k, nullptr, nullptr, DIM, KVDIM); }
__global__ __launch_bounds__(256, 2)
void gemm_v_mm() { gemm_mma_body<1>(g_xh, g_xl, g_wvTh, g_wvTl, nullptr, g_vh, g_vl, DIM, KVDIM); }
__global__ __launch_bounds__(256, 2)
void gemm_o_mm(float* __restrict__ out) { gemm_mma_body<0>(g_aoh, g_aol, g_woTh, g_woTl, out, nullptr, nullptr, DIM, DIM); }

// ---------------------------------------------------------------------------
// x -> bf16 hi/lo split
// ---------------------------------------------------------------------------
__global__ void convert_x_kernel(const float* __restrict__ x)
{
    int idx = blockIdx.x * blockDim.x + threadIdx.x;
    if (idx < TOKENS*DIM) {
        __nv_bfloat16 h, l;
        split1(x[idx], h, l);
        g_xh[idx] = h; g_xl[idx] = l;
    }
}

// transpose + split: w[K,N] -> wT_hi/lo[N,K]
__device__ __forceinline__
void transpose_split_body(const float* __restrict__ w, __nv_bfloat16* __restrict__ oh,
                          __nv_bfloat16* __restrict__ ol, int K, int N)
{
    __shared__ float tile[32][33];
    const int tx = threadIdx.x, ty = threadIdx.y;
    const int n0 = blockIdx.x * 32, k0 = blockIdx.y * 32;
#pragma unroll
    for (int j = 0; j < 4; j++) {
        int k = k0 + ty + j * 8;
        tile[ty + j * 8][tx] = w[(size_t)k * N + n0 + tx];
    }
    __syncthreads();
#pragma unroll
    for (int j = 0; j < 4; j++) {
        int n = n0 + ty + j * 8;
        float a = tile[tx][ty + j * 8];
        __nv_bfloat16 h, l; split1(a, h, l);
        oh[(size_t)n * K + k0 + tx] = h;
        ol[(size_t)n * K + k0 + tx] = l;
    }
}
__global__ void tsplit_wq(const float* __restrict__ w) { transpose_split_body(w, g_wqTh, g_wqTl, DIM, DIM); }
__global__ void tsplit_wk(const float* __restrict__ w) { transpose_split_body(w, g_wkTh, g_wkTl, DIM, KVDIM); }
__global__ void tsplit_wv(const float* __restrict__ w) { transpose_split_body(w, g_wvTh, g_wvTl, DIM, KVDIM); }
__global__ void tsplit_wo(const float* __restrict__ w) { transpose_split_body(w, g_woTh, g_woTl, DIM, DIM); }

// ---------------------------------------------------------------------------
// Fused RoPE + (optional scale) + bf16 split.
// in: fp32 [TOKENS, Hh*HD]; out: hi/lo bf16 same layout. pos = token % SEQ.
// ---------------------------------------------------------------------------
template <int Hh, bool SCALE>
__device__ __forceinline__
void rope_split_body(const float* __restrict__ in, __nv_bfloat16* __restrict__ oh,
                     __nv_bfloat16* __restrict__ ol, int total_pairs)
{
    int idx = blockIdx.x * blockDim.x + threadIdx.x;
    if (idx >= total_pairs) return;
    int i  = idx & 31;
    int t2 = idx >> 5;
    int h  = t2 % Hh;
    int t  = t2 / Hh;
    int pos = t & (SEQ - 1);
    const float LOG_THETA_OVER_32 = 0.28782313662425572f; // ln(10000)/32
    float freq = expf(-(float)i * LOG_THETA_OVER_32);
    float phase = (float)pos * freq;
    float s, c;
    sincosf(phase, &s, &c);
    size_t off = (size_t)t * (Hh * HD) + h * HD + 2 * i;
    float x0 = in[off], x1 = in[off + 1];
    float r0 = x0 * c - x1 * s;
    float r1 = x0 * s + x1 * c;
    if (SCALE) { r0 *= 0.125f; r1 *= 0.125f; }   // 1/sqrt(64), q only
    uint32_t hi, lo;
    split_pack2(r0, r1, hi, lo);
    *reinterpret_cast<uint32_t*>(oh + off) = hi;
    *reinterpret_cast<uint32_t*>(ol + off) = lo;
}
__global__ void rope_split_q(int total_pairs) { rope_split_body<NHEADS, true >(g_q, g_qh, g_ql, total_pairs); }
__global__ void rope_split_k(int total_pairs) { rope_split_body<NKV,    false>(g_k, g_kh, g_kl, total_pairs); }

// ---------------------------------------------------------------------------
// Tensor-core causal flash attention (GQA), bf16 split everywhere.
// Block: 64 queries of one (b,h); 128 threads (4 warps x 16 q-rows).
// Key tiles of 64. S = QhKh+QhKl+QlKh ; P split -> PhVh+PhVl+PlVh.
// Writes split bf16 attention output (aoh/aol) directly.
// ---------------------------------------------------------------------------
#define AQ 64
#define AK 64
// smem: Qh Ql Kh Kl Vh Vl, 8KB each (64 rows x 128B, SW128)
#define AS_QH 0
#define AS_QL 8192
#define AS_KH 16384
#define AS_KL 24576
#define AS_VH 32768
#define AS_VL 40960

__global__ __launch_bounds__(128, 4)
void attn_mma()
{
    __shared__ __align__(16) char sm[6 * 8192];
    const uint32_t sb = smem_u32(sm);

    const int tid = threadIdx.x, wid = tid >> 5, lane = tid & 31;
    const int qb = blockIdx.x, bh = blockIdx.y;
    const int b = bh / NHEADS, h = bh % NHEADS, j = h / REP;

    // Load Q tile (hi/lo) into smem
    for (int lin = tid; lin < 512; lin += 128) {
        int row = lin >> 3, ch = lin & 7;
        uint32_t so = SWZ128((uint32_t)(row * 128 + ch * 16));
        size_t g = (size_t)(b * SEQ + qb * AQ + row) * DIM + h * HD + ch * 8;
        *reinterpret_cast<uint4*>(sm + AS_QH + so) = *reinterpret_cast<const uint4*>(g_qh + g);
        *reinterpret_cast<uint4*>(sm + AS_QL + so) = *reinterpret_cast<const uint4*>(g_ql + g);
    }
    __syncthreads();

    // Q fragments (held for the whole kernel)
    uint32_t qfh[4][4], qfl[4][4];
    {
        const int ar = wid * 16 + (lane & 15);
        const int ac = lane >> 4;
#pragma unroll
        for (int t = 0; t < 4; t++) {
            uint32_t so = SWZ128((uint32_t)(ar * 128 + (t * 2 + ac) * 16));
            ldsm_x4(qfh[t], sb + AS_QH + so);
            ldsm_x4(qfl[t], sb + AS_QL + so);
        }
    }

    float oacc[8][4];
#pragma unroll
    for (int nj = 0; nj < 8; nj++)
#pragma unroll
        for (int r = 0; r < 4; r++) oacc[nj][r] = 0.0f;
    float m0 = -1e30f, m1 = -1e30f, l0 = 0.0f, l1 = 0.0f;

    const int br = (lane & 7) + ((lane & 16) >> 1);
    const int bc = (lane >> 3) & 1;
    const int vr = lane & 15;
    const int vc = lane >> 4;

    for (int kt = 0; kt <= qb; kt++) {
        __syncthreads();
        for (int lin = tid; lin < 512; lin += 128) {
            int row = lin >> 3, ch = lin & 7;
            uint32_t so = SWZ128((uint32_t)(row * 128 + ch * 16));
            size_t g = (size_t)(b * SEQ + kt * AK + row) * KVDIM + j * HD + ch * 8;
            *reinterpret_cast<uint4*>(sm + AS_KH + so) = *reinterpret_cast<const uint4*>(g_kh + g);
            *reinterpret_cast<uint4*>(sm + AS_KL + so) = *reinterpret_cast<const uint4*>(g_kl + g);
            *reinterpret_cast<uint4*>(sm + AS_VH + so) = *reinterpret_cast<const uint4*>(g_vh + g);
            *reinterpret_cast<uint4*>(sm + AS_VL + so) = *reinterpret_cast<const uint4*>(g_vl + g);
        }
        __syncthreads();

        // ---- S = Q K^T (split, fp32 acc) ----
        float sacc[8][4];
#pragma unroll
        for (int nj = 0; nj < 8; nj++)
#pragma unroll
            for (int r = 0; r < 4; r++) sacc[nj][r] = 0.0f;

#pragma unroll
        for (int t = 0; t < 4; t++) {
#pragma unroll
            for (int ng = 0; ng < 4; ng++) {
                uint32_t kh4[4], kl4[4];
                uint32_t so = SWZ128((uint32_t)((ng * 16 + br) * 128 + (t * 2 + bc) * 16));
                ldsm_x4(kh4, sb + AS_KH + so);
                ldsm_x4(kl4, sb + AS_KL + so);
#pragma unroll
                for (int hf = 0; hf < 2; hf++) {
                    int nj = ng * 2 + hf;
                    mma16816(sacc[nj], qfh[t], &kh4[hf * 2]);
                    mma16816(sacc[nj], qfh[t], &kl4[hf * 2]);
                    mma16816(sacc[nj], qfl[t], &kh4[hf * 2]);
                }
            }
        }

        // ---- causal mask on diagonal tile ----
        if (kt == qb) {
            int q0 = wid * 16 + (lane >> 2);
            int q1 = q0 + 8;
#pragma unroll
            for (int nj = 0; nj < 8; nj++) {
                int kl0 = nj * 8 + (lane & 3) * 2;
                if (kl0     > q0) sacc[nj][0] = -1e30f;
                if (kl0 + 1 > q0) sacc[nj][1] = -1e30f;
                if (kl0     > q1) sacc[nj][2] = -1e30f;
                if (kl0 + 1 > q1) sacc[nj][3] = -1e30f;
            }
        }

        // ---- online softmax ----
        float rm0 = -1e30f, rm1 = -1e30f;
#pragma unroll
        for (int nj = 0; nj < 8; nj++) {
            rm0 = fmaxf(rm0, fmaxf(sacc[nj][0], sacc[nj][1]));
            rm1 = fmaxf(rm1, fmaxf(sacc[nj][2], sacc[nj][3]));
        }
        rm0 = fmaxf(rm0, __shfl_xor_sync(0xffffffffu, rm0, 1));
        rm0 = fmaxf(rm0, __shfl_xor_sync(0xffffffffu, rm0, 2));
        rm1 = fmaxf(rm1, __shfl_xor_sync(0xffffffffu, rm1, 1));
        rm1 = fmaxf(rm1, __shfl_xor_sync(0xffffffffu, rm1, 2));

        float mn0 = fmaxf(m0, rm0), mn1 = fmaxf(m1, rm1);
        float c0 = __expf(m0 - mn0), c1 = __expf(m1 - mn1);
        l0 *= c0; l1 *= c1;
#pragma unroll
        for (int nj = 0; nj < 8; nj++) {
            oacc[nj][0] *= c0; oacc[nj][1] *= c0;
            oacc[nj][2] *= c1; oacc[nj][3] *= c1;
        }

        float ps0 = 0.0f, ps1 = 0.0f;
#pragma unroll
        for (int nj = 0; nj < 8; nj++) {
            float p0 = __expf(sacc[nj][0] - mn0);
            float p1 = __expf(sacc[nj][1] - mn0);
            float p2 = __expf(sacc[nj][2] - mn1);
            float p3 = __expf(sacc[nj][3] - mn1);
            ps0 += p0 + p1; ps1 += p2 + p3;
            sacc[nj][0] = p0; sacc[nj][1] = p1; sacc[nj][2] = p2; sacc[nj][3] = p3;
        }
        ps0 += __shfl_xor_sync(0xffffffffu, ps0, 1);
        ps0 += __shfl_xor_sync(0xffffffffu, ps0, 2);
        ps1 += __shfl_xor_sync(0xffffffffu, ps1, 1);
        ps1 += __shfl_xor_sync(0xffffffffu, ps1, 2);
        l0 += ps0; l1 += ps1;
        m0 = mn0; m1 = mn1;

        // ---- O += P V (split) ----
#pragma unroll
        for (int t = 0; t < 4; t++) {
            // P a-frags for key chunk t (keys 16t..16t+15) from sacc[2t],[2t+1]
            uint32_t pha[4], pla[4];
            split_pack2(sacc[2*t][0],   sacc[2*t][1],   pha[0], pla[0]);
            split_pack2(sacc[2*t][2],   sacc[2*t][3],   pha[1], pla[1]);
            split_pack2(sacc[2*t+1][0], sacc[2*t+1][1], pha[2], pla[2]);
            split_pack2(sacc[2*t+1][2], sacc[2*t+1][3], pha[3], pla[3]);
#pragma unroll
            for (int dp = 0; dp < 4; dp++) {
                uint32_t vh4[4], vl4[4];
                uint32_t so = SWZ128((uint32_t)((t * 16 + vr) * 128 + (dp * 2 + vc) * 16));
                ldsm_x4_t(vh4, sb + AS_VH + so);
                ldsm_x4_t(vl4, sb + AS_VL + so);
#pragma unroll
                for (int hf = 0; hf < 2; hf++) {
                    int nj = dp * 2 + hf;
                    mma16816(oacc[nj], pha, &vh4[hf * 2]);
                    mma16816(oacc[nj], pha, &vl4[hf * 2]);
                    mma16816(oacc[nj], pla, &vh4[hf * 2]);
                }
            }
        }
    }

    // ---- epilogue: normalize, split, store ----
    const float inv0 = 1.0f / l0, inv1 = 1.0f / l1;
    const int r0 = qb * AQ + wid * 16 + (lane >> 2);
    const size_t tok0 = (size_t)(b * SEQ + r0);
    const size_t tok1 = tok0 + 8;
#pragma unroll
    for (int nj = 0; nj < 8; nj++) {
        int col = h * HD + nj * 8 + (lane & 3) * 2;
        uint32_t h0, lo0, h1, lo1;
        split_pack2(oacc[nj][0] * inv0, oacc[nj][1] * inv0, h0, lo0);
        split_pack2(oacc[nj][2] * inv1, oacc[nj][3] * inv1, h1, lo1);
        *reinterpret_cast<uint32_t*>(g_aoh + tok0 * DIM + col) = h0;
        *reinterpret_cast<uint32_t*>(g_aol + tok0 * DIM + col) = lo0;
        *reinterpret_cast<uint32_t*>(g_aoh + tok1 * DIM + col) = h1;
        *reinterpret_cast<uint32_t*>(g_aol + tok1 * DIM + col) = lo1;
    }
}

// ---------------------------------------------------------------------------
// Launch
// ---------------------------------------------------------------------------
extern "C" void kernel_launch(void* const* d_in, const int* in_sizes, int n_in,
                              void* d_out, int out_size)
{
    const float* x  = (const float*)d_in[0];
    const float* wq = (const float*)d_in[1];
    const float* wk = (const float*)d_in[2];
    const float* wv = (const float*)d_in[3];
    const float* wo = (const float*)d_in[4];
    float* out = (float*)d_out;

    cudaFuncSetAttribute(gemm_q_mm, cudaFuncAttributeMaxDynamicSharedMemorySize, GEMM_SMEM_TOTAL);
    cudaFuncSetAttribute(gemm_k_mm, cudaFuncAttributeMaxDynamicSharedMemorySize, GEMM_SMEM_TOTAL);
    cudaFuncSetAttribute(gemm_v_mm, cudaFuncAttributeMaxDynamicSharedMemorySize, GEMM_SMEM_TOTAL);
    cudaFuncSetAttribute(gemm_o_mm, cudaFuncAttributeMaxDynamicSharedMemorySize, GEMM_SMEM_TOTAL);

    // 1) Input conversions
    {
        dim3 tb(32, 8);
        convert_x_kernel<<<(TOKENS*DIM + 255)/256, 256>>>(x);
        tsplit_wq<<<dim3(DIM/32,   DIM/32), tb>>>(wq);
        tsplit_wk<<<dim3(KVDIM/32, DIM/32), tb>>>(wk);
        tsplit_wv<<<dim3(KVDIM/32, DIM/32), tb>>>(wv);
        tsplit_wo<<<dim3(DIM/32,   DIM/32), tb>>>(wo);
    }

    // 2) Projections (V writes split bf16 directly)
    gemm_q_mm<<<dim3(DIM/128,   TOKENS/128), 256, GEMM_SMEM_TOTAL>>>();
    gemm_k_mm<<<dim3(KVDIM/128, TOKENS/128), 256, GEMM_SMEM_TOTAL>>>();
    gemm_v_mm<<<dim3(KVDIM/128, TOKENS/128), 256, GEMM_SMEM_TOTAL>>>();

    // 3) Fused RoPE + scale + split
    {
        int qpairs = TOKENS * NHEADS * (HD / 2);
        int kpairs = TOKENS * NKV    * (HD / 2);
        rope_split_q<<<(qpairs + 255) / 256, 256>>>(qpairs);
        rope_split_k<<<(kpairs + 255) / 256, 256>>>(kpairs);
    }

    // 4) Tensor-core flash attention (writes split bf16 ao)
    attn_mma<<<dim3(SEQ / AQ, BATCH * NHEADS), 128>>>();

    // 5) Output projection
    gemm_o_mm<<<dim3(DIM/128, TOKENS/128), 256, GEMM_SMEM_TOTAL>>>(out);
}